// round 11
// baseline (speedup 1.0000x reference)
#include <cuda_runtime.h>
#include <math.h>

#define G        512
#define S        32
#define PTS      8
#define SEGS_PER (PTS - 1)           // 7
#define NSEG     (S * SEGS_PER)      // 224
#define TILE     16
#define NTHREADS 64                  // 2 warps; 4 px/thread
#define TPR      (G / TILE)          // 32 tiles per row -> 1024 CTAs

// ---------------------------------------------------------------------------
// One 16x16 tile per 64-thread CTA (1024 CTAs; ~25 CTAs/SM -> ~50 warps/SM).
// Cull: 4 rounds (seg = r*64 + tid); each thread preloads its segments' points
//   + thickness straight from global before the first barrier (MLP batch).
//   Out-of-range lanes get 1e9 sentinels that self-cull. Warp-ballot compact
//   into a CTA list; survivor record = (vx,vy,ex,ey) + (fx,fy,sc,-) where
//   fx,fy = e*invd2 (frac needs no divide/multiply at render time).
// Render: 4 px/thread (rows ty,ty+8 x cols 2tx,2tx+1); neighbor fracs by
//   adds; 4 independent min chains; sqrt once; two float2 stores.
// ---------------------------------------------------------------------------
__global__ void __launch_bounds__(NTHREADS)
render_kernel(const float* __restrict__ strokes,
              const float* __restrict__ thick,
              float* __restrict__ out) {
    __shared__ float4 s_a[NSEG];     // vx, vy, ex, ey
    __shared__ float4 s_b[NSEG];     // fx, fy, sc, pad
    __shared__ int    s_n;

    const int tid  = threadIdx.x;
    const int lane = tid & 31;

    // ---- Preload all cull data (batched LDGs, latency under barrier) ----
    float2 P0[4], P1[4];
    float  TK[4];
    #pragma unroll
    for (int r = 0; r < 4; r++) {
        int seg = r * NTHREADS + tid;
        if (seg < NSEG) {
            int s = (seg * 9363) >> 16;              // seg / 7
            int i = s * PTS + (seg - s * SEGS_PER);  // point index
            P0[r] = ((const float2*)strokes)[i];
            P1[r] = ((const float2*)strokes)[i + 1];
            TK[r] = thick[s];
        } else {                                     // sentinel: self-culls
            P0[r] = make_float2(1e9f, 1e9f);
            P1[r] = P0[r];
            TK[r] = 0.0f;
        }
    }
    if (tid == 0) s_n = 0;
    __syncthreads();

    const int ti = blockIdx.y * TILE;                // row base (out stride G)
    const int tj = blockIdx.x * TILE;                // col base (contiguous)

    const float cx   = (float)ti + (TILE - 1) * 0.5f;
    const float cy   = (float)tj + (TILE - 1) * 0.5f;
    const float RMAX = (TILE - 1) * 0.5f * 1.41421356f + 1.0f;

    // ---- Cull: 4 rounds, ballot compaction (one atomic per warp/round) ----
    #pragma unroll
    for (int r = 0; r < 4; r++) {
        float vx = __saturatef(P0[r].x) * (float)G;
        float vy = __saturatef(P0[r].y) * (float)G;
        float wx = __saturatef(P1[r].x) * (float)G;
        float wy = __saturatef(P1[r].y) * (float)G;
        // sentinel: saturate(1e9)=1 -> v=w=(512,512) -> d2=0 -> center dist
        // from any tile center <= 724 ... must still self-cull: force far.
        if (P0[r].x > 2.0f) { vx = 1e9f; vy = 1e9f; wx = 1e9f; wy = 1e9f; }

        float ex = wx - vx;
        float ey = wy - vy;
        float d2 = ex * ex + ey * ey;
        float invd2 = __fdividef(1.0f, d2 + 1e-5f);
        float t  = fmaxf(fmaf(TK[r], 2.0f, 0.5f), 0.5f);
        float rr = 2.0f * t;

        float dx  = cx - vx;
        float dy  = cy - vy;
        float dot = dx * ex + dy * ey;
        float fr  = __saturatef(dot * invd2);
        float ddx = fmaf(-fr, ex, dx);
        float ddy = fmaf(-fr, ey, dy);
        float dq  = ddx * ddx + ddy * ddy;
        float thr = rr + RMAX;
        bool keep = (dq <= thr * thr);

        unsigned bal = __ballot_sync(0xffffffffu, keep);
        int base = 0;
        if (lane == 0 && bal) base = atomicAdd(&s_n, __popc(bal));
        base = __shfl_sync(0xffffffffu, base, 0);
        if (keep) {
            int p = base + __popc(bal & ((1u << lane) - 1u));
            s_a[p] = make_float4(vx, vy, ex, ey);
            s_b[p] = make_float4(ex * invd2, ey * invd2,
                                 __fdividef(1.0f, rr * rr), 0.0f);
        }
    }
    __syncthreads();

    // ---- Render: 4 px/thread (rows ty, ty+8; cols 2tx, 2tx+1) ----
    const int tx = tid & 7;                          // col pair base 2tx
    const int ty = tid >> 3;                         // 0..7
    const float px0 = (float)(ti + ty);
    const float py0 = (float)(tj + 2 * tx);
    const int n = s_n;

    float m00 = 1e30f, m01 = 1e30f, m10 = 1e30f, m11 = 1e30f;
    #pragma unroll 2
    for (int q = 0; q < n; q++) {
        float4 a = s_a[q];                           // vx vy ex ey
        float4 b = s_b[q];                           // fx fy sc -
        float dx0 = px0 - a.x;
        float dx1 = dx0 + 8.0f;
        float dy0 = py0 - a.y;
        float dy1 = dy0 + 1.0f;

        float f00 = fmaf(dx0, b.x, dy0 * b.y);       // frac at (r0,c0)
        float fx8 = 8.0f * b.x;
        float f01 = f00 + b.y;
        float f10 = f00 + fx8;
        float f11 = f10 + b.y;
        float u00 = __saturatef(f00);
        float u01 = __saturatef(f01);
        float u10 = __saturatef(f10);
        float u11 = __saturatef(f11);

        float e0 = a.z, e1 = a.w;
        float ddx00 = fmaf(-u00, e0, dx0), ddy00 = fmaf(-u00, e1, dy0);
        float ddx01 = fmaf(-u01, e0, dx0), ddy01 = fmaf(-u01, e1, dy1);
        float ddx10 = fmaf(-u10, e0, dx1), ddy10 = fmaf(-u10, e1, dy0);
        float ddx11 = fmaf(-u11, e0, dx1), ddy11 = fmaf(-u11, e1, dy1);

        float dq00 = fmaf(ddx00, ddx00, ddy00 * ddy00);
        float dq01 = fmaf(ddx01, ddx01, ddy01 * ddy01);
        float dq10 = fmaf(ddx10, ddx10, ddy10 * ddy10);
        float dq11 = fmaf(ddx11, ddx11, ddy11 * ddy11);

        m00 = fminf(m00, dq00 * b.z);
        m01 = fminf(m01, dq01 * b.z);
        m10 = fminf(m10, dq10 * b.z);
        m11 = fminf(m11, dq11 * b.z);
    }

    float2 r0 = make_float2(fminf(sqrtf(m00), 1.0f), fminf(sqrtf(m01), 1.0f));
    float2 r1 = make_float2(fminf(sqrtf(m10), 1.0f), fminf(sqrtf(m11), 1.0f));
    float* o = out + (ti + ty) * G + (tj + 2 * tx);
    *(float2*)o           = r0;
    *(float2*)(o + 8 * G) = r1;
}

extern "C" void kernel_launch(void* const* d_in, const int* in_sizes, int n_in,
                              void* d_out, int out_size) {
    // metadata order: strokes [32,8,2] f32 (512 elems), thicknesses [32] f32.
    const float* strokes = (const float*)d_in[0];
    const float* thick   = (const float*)d_in[1];
    if (n_in >= 2 && in_sizes[0] == S && in_sizes[1] == S * PTS * 2) {
        strokes = (const float*)d_in[1];
        thick   = (const float*)d_in[0];
    }
    float* out = (float*)d_out;

    dim3 block(NTHREADS);
    dim3 grid(TPR, TPR);
    render_kernel<<<grid, block>>>(strokes, thick, out);
}

// round 12
// speedup vs baseline: 1.3942x; 1.3942x over previous
#include <cuda_runtime.h>
#include <math.h>

#define G        512
#define S        32
#define PTS      8
#define SEGS_PER (PTS - 1)           // 7
#define NSEG     (S * SEGS_PER)      // 224
#define TILE     16
#define NTHREADS 256                 // 1 px/thread, 8 warps/CTA
#define TPR      (G / TILE)          // 32 tiles per row -> 1024 CTAs

// ---------------------------------------------------------------------------
// One 16x16 tile per 256-thread CTA (1024 CTAs, ~7 CTAs/SM -> ~55 warps/SM).
// Maximizes resident warps (TLP) to hide LDS/LDG/barrier latency that pinned
// every lower-occupancy variant at ~6 us.
// Cull: single round - thread t < 224 owns segment t (points + thickness
//   preloaded before the first barrier; out-of-range lanes carry sentinels
//   that self-cull). Warp-ballot compaction, <=7 shared atomics total.
//   Survivor record: (vx,vy,ex,ey) + (fx,fy,sc,-), fx,fy = e*invd2.
// Render: 1 pixel/thread, ~7 survivor iterations; min of scaled squared
//   distance; single sqrt; coalesced scalar store.
// ---------------------------------------------------------------------------
__global__ void __launch_bounds__(NTHREADS)
render_kernel(const float* __restrict__ strokes,
              const float* __restrict__ thick,
              float* __restrict__ out) {
    __shared__ float4 s_a[NSEG];     // vx, vy, ex, ey
    __shared__ float4 s_b[NSEG];     // fx, fy, sc, pad
    __shared__ int    s_n;

    const int tid  = threadIdx.x;
    const int lane = tid & 31;

    // ---- Preload cull data (latency hides under the first barrier) ----
    float2 p0 = make_float2(1e9f, 1e9f), p1 = p0;
    float  tk = 0.0f;
    if (tid < NSEG) {
        int s = (tid * 9363) >> 16;              // tid / 7
        int i = s * PTS + (tid - s * SEGS_PER);  // point index
        p0 = ((const float2*)strokes)[i];
        p1 = ((const float2*)strokes)[i + 1];
        tk = thick[s];
    }
    if (tid == 0) s_n = 0;
    __syncthreads();

    const int ti = blockIdx.y * TILE;            // row base (out stride G)
    const int tj = blockIdx.x * TILE;            // col base (contiguous)

    const float cx   = (float)ti + (TILE - 1) * 0.5f;
    const float cy   = (float)tj + (TILE - 1) * 0.5f;
    const float RMAX = (TILE - 1) * 0.5f * 1.41421356f + 1.0f;

    // ---- Cull: one round, ballot compaction ----
    {
        float vx = __saturatef(p0.x) * (float)G;
        float vy = __saturatef(p0.y) * (float)G;
        float wx = __saturatef(p1.x) * (float)G;
        float wy = __saturatef(p1.y) * (float)G;
        if (p0.x > 2.0f) { vx = 1e9f; vy = 1e9f; wx = 1e9f; wy = 1e9f; }

        float ex = wx - vx;
        float ey = wy - vy;
        float d2 = ex * ex + ey * ey;
        float invd2 = __fdividef(1.0f, d2 + 1e-5f);
        float t  = fmaxf(fmaf(tk, 2.0f, 0.5f), 0.5f);
        float rr = 2.0f * t;

        float dx  = cx - vx;
        float dy  = cy - vy;
        float dot = dx * ex + dy * ey;
        float fr  = __saturatef(dot * invd2);
        float ddx = fmaf(-fr, ex, dx);
        float ddy = fmaf(-fr, ey, dy);
        float dq  = ddx * ddx + ddy * ddy;
        float thr = rr + RMAX;
        bool keep = (dq <= thr * thr);

        unsigned bal = __ballot_sync(0xffffffffu, keep);
        int base = 0;
        if (lane == 0 && bal) base = atomicAdd(&s_n, __popc(bal));
        base = __shfl_sync(0xffffffffu, base, 0);
        if (keep) {
            int p = base + __popc(bal & ((1u << lane) - 1u));
            s_a[p] = make_float4(vx, vy, ex, ey);
            s_b[p] = make_float4(ex * invd2, ey * invd2,
                                 __fdividef(1.0f, rr * rr), 0.0f);
        }
    }
    __syncthreads();

    // ---- Render: 1 pixel per thread ----
    const int tx = tid & (TILE - 1);             // col 0..15
    const int ty = tid >> 4;                     // row 0..15
    const float px = (float)(ti + ty);
    const float py = (float)(tj + tx);
    const int n = s_n;

    float m = 1e30f;
    #pragma unroll 4
    for (int q = 0; q < n; q++) {
        float4 a = s_a[q];                       // vx vy ex ey
        float4 b = s_b[q];                       // fx fy sc -
        float dx = px - a.x;
        float dy = py - a.y;
        float fr = __saturatef(fmaf(dx, b.x, dy * b.y));
        float ddx = fmaf(-fr, a.z, dx);
        float ddy = fmaf(-fr, a.w, dy);
        float dq  = fmaf(ddx, ddx, ddy * ddy);
        m = fminf(m, dq * b.z);
    }

    out[(ti + ty) * G + (tj + tx)] = fminf(sqrtf(m), 1.0f);
}

extern "C" void kernel_launch(void* const* d_in, const int* in_sizes, int n_in,
                              void* d_out, int out_size) {
    // metadata order: strokes [32,8,2] f32 (512 elems), thicknesses [32] f32.
    const float* strokes = (const float*)d_in[0];
    const float* thick   = (const float*)d_in[1];
    if (n_in >= 2 && in_sizes[0] == S && in_sizes[1] == S * PTS * 2) {
        strokes = (const float*)d_in[1];
        thick   = (const float*)d_in[0];
    }
    float* out = (float*)d_out;

    dim3 block(NTHREADS);
    dim3 grid(TPR, TPR);
    render_kernel<<<grid, block>>>(strokes, thick, out);
}